// round 14
// baseline (speedup 1.0000x reference)
#include <cuda_runtime.h>
#include <cuda_fp16.h>
#include <cstdint>

// ---------------- problem dims (fixed) ----------------
#define B_   4
#define L_   2048
#define DM   1024      // d_model
#define DI   2048      // d_inner
#define DS   32        // d_state
#define DR   64        // dt_rank
#define M_   (B_ * L_) // 8192 rows
#define LN_EPS 1e-5f

// ---------------- scratch (device globals; no allocs allowed) ----------------
__device__ __align__(256) float g_dbc[(size_t)M_ * 128];     // dt|B|C fp32
__device__ __align__(256) float g_delta[(size_t)M_ * DI];    // softplus fp32

// fp16 buffers
__device__ __align__(256) half g_xzh[(size_t)M_ * 2 * DI];   // xi | z fp16
__device__ __align__(256) half g_xh[(size_t)M_ * DM];
__device__ __align__(256) half g_uh[(size_t)M_ * DI];
__device__ __align__(256) half g_dth[(size_t)M_ * DR];
__device__ __align__(256) half g_yh[(size_t)M_ * DI];
// weights, converted + transposed to [N, K] fp16
__device__ __align__(256) half g_win[(size_t)4096 * DM];
__device__ __align__(256) half g_wxp[(size_t)128 * DI];
__device__ __align__(256) half g_wdt[(size_t)DI * DR];
__device__ __align__(256) half g_wout[(size_t)DM * DI];

// ---------------- helpers ----------------
__device__ __forceinline__ float siluf(float x) { return x / (1.f + expf(-x)); }
__device__ __forceinline__ float softplusf(float x) {
    return (x > 20.f) ? x : log1pf(expf(x));
}
__device__ __forceinline__ float ex2f(float x) {
    float y; asm("ex2.approx.ftz.f32 %0, %1;" : "=f"(y) : "f"(x)); return y;
}
__device__ __forceinline__ uint32_t smem_u32(const void* p) {
    return (uint32_t)__cvta_generic_to_shared(p);
}
__device__ __forceinline__ void cp16(uint32_t dst, const void* src) {
    asm volatile("cp.async.cg.shared.global [%0], [%1], 16;" :: "r"(dst), "l"(src));
}
__device__ __forceinline__ void ldm4(uint32_t* r, uint32_t addr) {
    asm volatile("ldmatrix.sync.aligned.m8n8.x4.shared.b16 {%0,%1,%2,%3}, [%4];"
                 : "=r"(r[0]), "=r"(r[1]), "=r"(r[2]), "=r"(r[3]) : "r"(addr));
}
__device__ __forceinline__ void mma16816(float* c, const uint32_t* a,
                                         uint32_t b0, uint32_t b1) {
    asm volatile(
        "mma.sync.aligned.m16n8k16.row.col.f32.f16.f16.f32 "
        "{%0,%1,%2,%3}, {%4,%5,%6,%7}, {%8,%9}, {%0,%1,%2,%3};"
        : "+f"(c[0]), "+f"(c[1]), "+f"(c[2]), "+f"(c[3])
        : "r"(a[0]), "r"(a[1]), "r"(a[2]), "r"(a[3]), "r"(b0), "r"(b1));
}

#define ROWB 80
#define APB  10240            // 128 rows * 80B
#define STGB 20480            // one stage: A(128x80) + B(128x80)

// ---------------- fp16 GEMM: 128x128 tile, 256 thr, 3-stage pipeline ----------------
// C[M,N] = Ah[M,K(lda)] x (Bh[N,K(lda)])^T, fp32 accum.
// ACT: 0 fp32 out, 1 softplus(+bias) fp32 out, 3 fp16 out, 4 fp32 accumulate (C +=).
template<int ACT>
__global__ void __launch_bounds__(256, 2)
mma_gemm(const half* __restrict__ Ah, const half* __restrict__ Bh,
         const float* __restrict__ bias, float* __restrict__ C,
         int K, int lda, int ldc) {
    extern __shared__ char smem[];
    const uint32_t sbase = smem_u32(smem);
    const int tid = threadIdx.x;
    const int lane = tid & 31, wid = tid >> 5;
    const int warp_m = wid >> 1, warp_n = wid & 1;
    const int bm = blockIdx.y * 128, bn = blockIdx.x * 128;

    float acc[2][8][4];
#pragma unroll
    for (int i = 0; i < 2; i++)
#pragma unroll
        for (int j = 0; j < 8; j++)
#pragma unroll
            for (int k = 0; k < 4; k++) acc[i][j][k] = 0.f;

    const int NK = K >> 5;

    auto stage_load = [&](int kt, uint32_t sb) {
        const int k0 = kt << 5;
#pragma unroll
        for (int ii = 0; ii < 2; ii++) {
            const int i = tid + ii * 256;
            const int r = i >> 2, c = i & 3;
            cp16(sb + (uint32_t)(r * ROWB + c * 16),
                 Ah + (size_t)(bm + r) * lda + k0 + c * 8);
        }
#pragma unroll
        for (int ii = 0; ii < 2; ii++) {
            const int i = tid + ii * 256;
            const int r = i >> 2, c = i & 3;
            cp16(sb + APB + (uint32_t)(r * ROWB + c * 16),
                 Bh + (size_t)(bn + r) * lda + k0 + c * 8);
        }
    };

    stage_load(0, sbase);
    asm volatile("cp.async.commit_group;" ::: "memory");
    stage_load(1, sbase + STGB);
    asm volatile("cp.async.commit_group;" ::: "memory");

    const int rsel = lane & 15, ksel = lane >> 4;
    int buf = 0, lbuf = 2;

    for (int kt = 0; kt < NK; kt++) {
        asm volatile("cp.async.wait_group 1;" ::: "memory");
        __syncthreads();
        if (kt + 2 < NK)
            stage_load(kt + 2, sbase + lbuf * STGB);
        asm volatile("cp.async.commit_group;" ::: "memory");

        const uint32_t sb = sbase + buf * STGB;
#pragma unroll
        for (int ks = 0; ks < 2; ks++) {
            uint32_t aH[2][4], bH[4][4];
            const uint32_t ko = (uint32_t)(ks * 2 + ksel) * 16;
#pragma unroll
            for (int i = 0; i < 2; i++) {
                const uint32_t off = (uint32_t)(warp_m * 32 + i * 16 + rsel) * ROWB + ko;
                ldm4(aH[i], sb + off);
            }
#pragma unroll
            for (int j = 0; j < 4; j++) {
                const uint32_t off = (uint32_t)(warp_n * 64 + j * 16 + rsel) * ROWB + ko;
                ldm4(bH[j], sb + APB + off);
            }
#pragma unroll
            for (int i = 0; i < 2; i++)
#pragma unroll
                for (int jj = 0; jj < 8; jj++) {
                    const int j = jj >> 1, s2 = jj & 1;
                    mma16816(acc[i][jj], aH[i], bH[j][s2], bH[j][s2 + 2]);
                }
        }
        buf = (buf == 2) ? 0 : buf + 1;
        lbuf = (lbuf == 2) ? 0 : lbuf + 1;
    }

    // epilogue
    const int g  = lane >> 2;
    const int tq = lane & 3;
#pragma unroll
    for (int i = 0; i < 2; i++) {
        const int row0 = bm + warp_m * 32 + i * 16 + g;
#pragma unroll
        for (int jj = 0; jj < 8; jj++) {
            const int col = bn + warp_n * 64 + jj * 8 + 2 * tq;
            float2 v0 = make_float2(acc[i][jj][0], acc[i][jj][1]);
            float2 v1 = make_float2(acc[i][jj][2], acc[i][jj][3]);
            if (ACT == 1) {
                const float bb0 = bias[col], bb1 = bias[col + 1];
                v0.x = softplusf(v0.x + bb0); v0.y = softplusf(v0.y + bb1);
                v1.x = softplusf(v1.x + bb0); v1.y = softplusf(v1.y + bb1);
            }
            if (ACT == 3) {
                half* C16 = (half*)C;
                *(__half2*)&C16[(size_t)row0 * ldc + col] =
                    __floats2half2_rn(v0.x, v0.y);
                *(__half2*)&C16[(size_t)(row0 + 8) * ldc + col] =
                    __floats2half2_rn(v1.x, v1.y);
            } else {
                if (ACT == 4) {
                    float2 o0 = *(float2*)&C[(size_t)row0 * ldc + col];
                    float2 o1 = *(float2*)&C[(size_t)(row0 + 8) * ldc + col];
                    v0.x += o0.x; v0.y += o0.y;
                    v1.x += o1.x; v1.y += o1.y;
                }
                *(float2*)&C[(size_t)row0 * ldc + col] = v0;
                *(float2*)&C[(size_t)(row0 + 8) * ldc + col] = v1;
            }
        }
    }
}

// ---------------- x_proj GEMM (BN=64, fused dt fp16 emit) ----------------
__global__ void __launch_bounds__(256)
mma_gemm_xp(const half* __restrict__ Ah, const half* __restrict__ Bh,
            float* __restrict__ C, half* __restrict__ dth,
            int K, int ldc) {
    constexpr int BPB = 64 * ROWB;
    constexpr int STG = APB + BPB;

    extern __shared__ char smem[];
    const uint32_t sbase = smem_u32(smem);
    const int tid = threadIdx.x;
    const int lane = tid & 31, wid = tid >> 5;
    const int warp_m = wid >> 1, warp_n = wid & 1;
    const int bm = blockIdx.y * 128, bn = blockIdx.x * 64;

    float acc[2][4][4];
#pragma unroll
    for (int i = 0; i < 2; i++)
#pragma unroll
        for (int t = 0; t < 4; t++)
#pragma unroll
            for (int k = 0; k < 4; k++) acc[i][t][k] = 0.f;

    const int NK = K >> 5;

    auto stage_load = [&](int kt, uint32_t sb) {
        const int k0 = kt << 5;
#pragma unroll
        for (int ii = 0; ii < 2; ii++) {
            const int i = tid + ii * 256;
            const int r = i >> 2, c = i & 3;
            cp16(sb + (uint32_t)(r * ROWB + c * 16),
                 Ah + (size_t)(bm + r) * K + k0 + c * 8);
        }
        {
            const int r = tid >> 2, c = tid & 3;
            if (r < 64)
                cp16(sb + APB + (uint32_t)(r * ROWB + c * 16),
                     Bh + (size_t)(bn + r) * K + k0 + c * 8);
        }
    };

    stage_load(0, sbase);
    asm volatile("cp.async.commit_group;" ::: "memory");

    const int rsel = lane & 15, ksel = lane >> 4;

    for (int kt = 0; kt < NK; kt++) {
        if (kt + 1 < NK)
            stage_load(kt + 1, sbase + ((kt + 1) & 1) * STG);
        asm volatile("cp.async.commit_group;" ::: "memory");
        asm volatile("cp.async.wait_group 1;" ::: "memory");
        __syncthreads();

        const uint32_t sb = sbase + (kt & 1) * STG;
#pragma unroll
        for (int ks = 0; ks < 2; ks++) {
            uint32_t aH[2][4], bH[2][4];
            const uint32_t ko = (uint32_t)(ks * 2 + ksel) * 16;
#pragma unroll
            for (int i = 0; i < 2; i++) {
                const uint32_t off = (uint32_t)(warp_m * 32 + i * 16 + rsel) * ROWB + ko;
                ldm4(aH[i], sb + off);
            }
#pragma unroll
            for (int j = 0; j < 2; j++) {
                const uint32_t off = (uint32_t)(warp_n * 32 + j * 16 + rsel) * ROWB + ko;
                ldm4(bH[j], sb + APB + off);
            }
#pragma unroll
            for (int i = 0; i < 2; i++)
#pragma unroll
                for (int t = 0; t < 4; t++) {
                    const int j = t >> 1, s2 = t & 1;
                    mma16816(acc[i][t], aH[i], bH[j][s2], bH[j][s2 + 2]);
                }
        }
        __syncthreads();
    }

    const int g  = lane >> 2;
    const int tq = lane & 3;
#pragma unroll
    for (int i = 0; i < 2; i++) {
        const int row0 = bm + warp_m * 32 + i * 16 + g;
#pragma unroll
        for (int t = 0; t < 4; t++) {
            const int col = bn + warp_n * 32 + t * 8 + 2 * tq;
            float2 v0 = make_float2(acc[i][t][0], acc[i][t][1]);
            float2 v1 = make_float2(acc[i][t][2], acc[i][t][3]);
            *(float2*)&C[(size_t)row0 * ldc + col] = v0;
            *(float2*)&C[(size_t)(row0 + 8) * ldc + col] = v1;
            if (blockIdx.x == 0) {   // cols 0..63 = dt
                dth[(size_t)row0 * DR + col]           = __float2half(v0.x);
                dth[(size_t)row0 * DR + col + 1]       = __float2half(v0.y);
                dth[(size_t)(row0 + 8) * DR + col]     = __float2half(v1.x);
                dth[(size_t)(row0 + 8) * DR + col + 1] = __float2half(v1.y);
            }
        }
    }
}

// ---------------- producers: fp16 convert ----------------
__global__ void conv16_kernel(const float2* __restrict__ src,
                              uint32_t* __restrict__ hi, int n2) {
    int i = blockIdx.x * blockDim.x + threadIdx.x;
    if (i >= n2) return;
    float2 f = src[i];
    half h0 = __float2half(f.x), h1 = __float2half(f.y);
    hi[i] = (uint32_t)__half_as_ushort(h0) | ((uint32_t)__half_as_ushort(h1) << 16);
}

// weights: src [K,N] fp32 -> dst [N,K] fp16
__global__ void tconv_kernel(const float* __restrict__ src,
                             half* __restrict__ dst, int K, int N) {
    __shared__ float t[32][33];
    const int k0 = blockIdx.y * 32, n0 = blockIdx.x * 32;
    const int tx = threadIdx.x, ty = threadIdx.y;
#pragma unroll
    for (int i = 0; i < 32; i += 8)
        t[ty + i][tx] = src[(size_t)(k0 + ty + i) * N + n0 + tx];
    __syncthreads();
#pragma unroll
    for (int i = 0; i < 32; i += 8)
        dst[(size_t)(n0 + ty + i) * K + k0 + tx] = __float2half(t[tx][ty + i]);
}

// ---------------- causal conv1d (D_CONV=4) + silu, half2 vectorized ----------------
__global__ void conv_silu_kernel(const half* __restrict__ xzh,
                                 const float* __restrict__ cw,
                                 const float* __restrict__ cb,
                                 half* __restrict__ uh) {
    int idx = blockIdx.x * blockDim.x + threadIdx.x;   // over M_*DI/2
    if (idx >= M_ * DI / 2) return;
    const int d2 = idx & (DI / 2 - 1);                 // half2 col
    const int t  = (idx >> 10) & (L_ - 1);
    const int b  = idx >> 21;
    const int d  = d2 * 2;

    const float4 w0 = ((const float4*)cw)[d];
    const float4 w1 = ((const float4*)cw)[d + 1];
    float a0 = cb[d], a1 = cb[d + 1];

    const __half2* p = (const __half2*)xzh;
    const size_t rb = (size_t)(b * L_) * DI + d2;

    if (t >= 3) {
        float2 f;
        f = __half22float2(p[rb + (size_t)(t - 3) * DI]);
        a0 = fmaf(f.x, w0.x, a0); a1 = fmaf(f.y, w1.x, a1);
        f = __half22float2(p[rb + (size_t)(t - 2) * DI]);
        a0 = fmaf(f.x, w0.y, a0); a1 = fmaf(f.y, w1.y, a1);
        f = __half22float2(p[rb + (size_t)(t - 1) * DI]);
        a0 = fmaf(f.x, w0.z, a0); a1 = fmaf(f.y, w1.z, a1);
        f = __half22float2(p[rb + (size_t)(t    ) * DI]);
        a0 = fmaf(f.x, w0.w, a0); a1 = fmaf(f.y, w1.w, a1);
    } else {
        const float wk0[4] = {w0.x, w0.y, w0.z, w0.w};
        const float wk1[4] = {w1.x, w1.y, w1.z, w1.w};
#pragma unroll
        for (int k = 0; k < 4; k++) {
            int tt = t + k - 3;
            if (tt >= 0) {
                float2 f = __half22float2(p[rb + (size_t)tt * DI]);
                a0 = fmaf(f.x, wk0[k], a0); a1 = fmaf(f.y, wk1[k], a1);
            }
        }
    }
    ((__half2*)uh)[(size_t)(b * L_ + t) * (DI / 2) + d2] =
        __floats2half2_rn(siluf(a0), siluf(a1));
}

// ---------------- selective scan + gating (64-step tiles, 16-step reduce) ----------------
// d-range split: handles channels [doff, doff + gridDim.x*8)
__global__ void __launch_bounds__(256)
scan_kernel(const float* __restrict__ delta,
            const half* __restrict__ uh,
            const float* __restrict__ dbc,
            const float* __restrict__ A_log,
            const float* __restrict__ Dp,
            const half* __restrict__ xzh,
            half* __restrict__ yh, int doff) {
    const int lane = threadIdx.x & 31;
    const int w    = threadIdx.x >> 5;            // 0..7
    const int d0   = doff + blockIdx.x * 8;
    const int b    = blockIdx.y;

    __shared__ float2 sBC[64][32];                // [t][s] = (B, C)
    __shared__ float2 sDP[64][8];                 // [t][w] = (delta, delta*u)
    __shared__ float  sh[64][9];                  // output transpose, padded

    const float A2 = -expf(A_log[(d0 + w) * DS + lane]) * 1.4426950408889634f;

    const int lt = threadIdx.x >> 3;              // 0..31
    const int lq = threadIdx.x & 7;               // 0..7
    const float Dv = Dp[d0 + lq];

    float h = 0.f;

    for (int t0 = 0; t0 < L_; t0 += 64) {
        float uu[2], zz[2];
#pragma unroll
        for (int rr = 0; rr < 2; rr++) {
            const int row = lt + rr * 32;
            const size_t lrow = (size_t)(b * L_ + t0 + row);
            const float4* src = (const float4*)(dbc + lrow * 128 + 64);
            const float4 B4 = src[lq];
            const float4 C4 = src[lq + 8];
            sBC[row][lq * 4 + 0] = make_float2(B4.x, C4.x);
            sBC[row][lq * 4 + 1] = make_float2(B4.y, C4.y);
            sBC[row][lq * 4 + 2] = make_float2(B4.z, C4.z);
            sBC[row][lq * 4 + 3] = make_float2(B4.w, C4.w);
            const float dl = delta[lrow * DI + d0 + lq];
            uu[rr] = __half2float(uh[lrow * DI + d0 + lq]);
            zz[rr] = __half2float(xzh[lrow * (size_t)(2 * DI) + DI + d0 + lq]);
            sDP[row][lq] = make_float2(dl, dl * uu[rr]);
        }
        __syncthreads();

#pragma unroll
        for (int ch = 0; ch < 4; ch++) {
            float v[16];
#pragma unroll
            for (int ti = 0; ti < 16; ti++) {
                const int tt = ch * 16 + ti;
                const float2 dp = sDP[tt][w];
                const float2 bc = sBC[tt][lane];
                h = fmaf(ex2f(dp.x * A2), h, dp.y * bc.x);
                v[ti] = h * bc.y;
            }
            const bool hi8 = (lane & 8) != 0;
#pragma unroll
            for (int j = 0; j < 8; j++) {
                float send = hi8 ? v[j] : v[j + 8];
                float r = __shfl_xor_sync(0xffffffffu, send, 8);
                v[j] = (hi8 ? v[j + 8] : v[j]) + r;
            }
            const bool hi4 = (lane & 4) != 0;
#pragma unroll
            for (int j = 0; j < 4; j++) {
                float send = hi4 ? v[j] : v[j + 4];
                float r = __shfl_xor_sync(0xffffffffu, send, 4);
                v[j] = (hi4 ? v[j + 4] : v[j]) + r;
            }
            const bool hi2 = (lane & 2) != 0;
#pragma unroll
            for (int j = 0; j < 2; j++) {
                float send = hi2 ? v[j] : v[j + 2];
                float r = __shfl_xor_sync(0xffffffffu, send, 2);
                v[j] = (hi2 ? v[j + 2] : v[j]) + r;
            }
            const bool hi1 = (lane & 1) != 0;
            {
                float send = hi1 ? v[0] : v[1];
                float r = __shfl_xor_sync(0xffffffffu, send, 1);
                v[0] = (hi1 ? v[1] : v[0]) + r;
            }
            v[0] += __shfl_xor_sync(0xffffffffu, v[0], 16);
            if (lane < 16) sh[ch * 16 + lane][w] = v[0];
        }
        __syncthreads();

#pragma unroll
        for (int rr = 0; rr < 2; rr++) {
            const int row = lt + rr * 32;
            const size_t lrow = (size_t)(b * L_ + t0 + row);
            const float yv = sh[row][lq];
            const float yf = (yv + uu[rr] * Dv) * siluf(zz[rr]);
            yh[lrow * DI + d0 + lq] = __float2half(yf);
        }
        __syncthreads();
    }
}

// ---------------- in-place LayerNorm (row = 1024) ----------------
__global__ void ln_kernel(float* __restrict__ out,
                          const float* __restrict__ gamma,
                          const float* __restrict__ beta) {
    const int row = blockIdx.x;
    float4* p = (float4*)(out + (size_t)row * DM);
    const int i = threadIdx.x;

    float4 x = p[i];
    float s = x.x + x.y + x.z + x.w;
    float q = x.x * x.x + x.y * x.y + x.z * x.z + x.w * x.w;
#pragma unroll
    for (int o = 16; o; o >>= 1) {
        s += __shfl_xor_sync(0xffffffffu, s, o);
        q += __shfl_xor_sync(0xffffffffu, q, o);
    }
    __shared__ float rs[8], rq[8];
    if ((i & 31) == 0) { rs[i >> 5] = s; rq[i >> 5] = q; }
    __syncthreads();
    s = 0.f; q = 0.f;
#pragma unroll
    for (int k = 0; k < 8; k++) { s += rs[k]; q += rq[k]; }

    const float mu  = s * (1.f / DM);
    const float var = q * (1.f / DM) - mu * mu;
    const float inv = rsqrtf(var + LN_EPS);

    const float4 gg = ((const float4*)gamma)[i];
    const float4 bb = ((const float4*)beta)[i];
    x.x = (x.x - mu) * inv * gg.x + bb.x;
    x.y = (x.y - mu) * inv * gg.y + bb.y;
    x.z = (x.z - mu) * inv * gg.z + bb.z;
    x.w = (x.w - mu) * inv * gg.w + bb.w;
    p[i] = x;
}

// ---------------- launch ----------------
extern "C" void kernel_launch(void* const* d_in, const int* in_sizes, int n_in,
                              void* d_out, int out_size) {
    (void)in_sizes; (void)n_in; (void)out_size;
    const float* x         = (const float*)d_in[0];
    const float* in_proj_w = (const float*)d_in[1];
    const float* conv_w    = (const float*)d_in[2];
    const float* conv_b    = (const float*)d_in[3];
    const float* x_proj_w  = (const float*)d_in[4];
    const float* dt_proj_w = (const float*)d_in[5];
    const float* dt_proj_b = (const float*)d_in[6];
    const float* A_log     = (const float*)d_in[7];
    const float* Dp        = (const float*)d_in[8];
    const float* out_proj_w= (const float*)d_in[9];
    const float* ln_gamma  = (const float*)d_in[10];
    const float* ln_beta   = (const float*)d_in[11];
    float* out = (float*)d_out;

    float *dbc, *delta;
    half *xzh, *xh, *uh, *dth, *yh;
    half *win, *wxp, *wdt, *wout;
    cudaGetSymbolAddress((void**)&dbc,   g_dbc);
    cudaGetSymbolAddress((void**)&delta, g_delta);
    cudaGetSymbolAddress((void**)&xzh,   g_xzh);
    cudaGetSymbolAddress((void**)&xh,    g_xh);
    cudaGetSymbolAddress((void**)&uh,    g_uh);
    cudaGetSymbolAddress((void**)&dth,   g_dth);
    cudaGetSymbolAddress((void**)&yh,    g_yh);
    cudaGetSymbolAddress((void**)&win,   g_win);
    cudaGetSymbolAddress((void**)&wxp,   g_wxp);
    cudaGetSymbolAddress((void**)&wdt,   g_wdt);
    cudaGetSymbolAddress((void**)&wout,  g_wout);

    constexpr int SMEM_P3 = 3 * STGB;          // 61440
    constexpr int STG_XP  = APB + 64 * ROWB;   // 15360
    constexpr int SMEM_XP = 2 * STG_XP;        // 30720
    cudaFuncSetAttribute(mma_gemm<0>, cudaFuncAttributeMaxDynamicSharedMemorySize, SMEM_P3);
    cudaFuncSetAttribute(mma_gemm<1>, cudaFuncAttributeMaxDynamicSharedMemorySize, SMEM_P3);
    cudaFuncSetAttribute(mma_gemm<3>, cudaFuncAttributeMaxDynamicSharedMemorySize, SMEM_P3);
    cudaFuncSetAttribute(mma_gemm<4>, cudaFuncAttributeMaxDynamicSharedMemorySize, SMEM_P3);
    cudaFuncSetAttribute(mma_gemm_xp, cudaFuncAttributeMaxDynamicSharedMemorySize, SMEM_XP);

    // streams/events (created once; handles only)
    static cudaStream_t s1 = nullptr, s2 = nullptr;
    static cudaEvent_t e0 = nullptr, e_win = nullptr, e_xh = nullptr,
                       e_w = nullptr, e_z = nullptr, e_xp = nullptr,
                       e_dtp1 = nullptr, e_s0 = nullptr, e_s1 = nullptr,
                       e_done = nullptr;
    if (s1 == nullptr) {
        cudaStreamCreateWithFlags(&s1, cudaStreamNonBlocking);
        cudaStreamCreateWithFlags(&s2, cudaStreamNonBlocking);
        cudaEventCreateWithFlags(&e0,    cudaEventDisableTiming);
        cudaEventCreateWithFlags(&e_win, cudaEventDisableTiming);
        cudaEventCreateWithFlags(&e_xh,  cudaEventDisableTiming);
        cudaEventCreateWithFlags(&e_w,   cudaEventDisableTiming);
        cudaEventCreateWithFlags(&e_z,   cudaEventDisableTiming);
        cudaEventCreateWithFlags(&e_xp,  cudaEventDisableTiming);
        cudaEventCreateWithFlags(&e_dtp1,cudaEventDisableTiming);
        cudaEventCreateWithFlags(&e_s0,  cudaEventDisableTiming);
        cudaEventCreateWithFlags(&e_s1,  cudaEventDisableTiming);
        cudaEventCreateWithFlags(&e_done,cudaEventDisableTiming);
    }

    // fork point
    cudaEventRecord(e0, 0);

    // --- s1: x convert, then (after win) the z-half GEMM ---
    cudaStreamWaitEvent(s1, e0, 0);
    conv16_kernel<<<(M_*DM/2 + 255)/256, 256, 0, s1>>>(
        (const float2*)x, (uint32_t*)xh, M_*DM/2);
    cudaEventRecord(e_xh, s1);

    // --- s2: weight transposes needed from x_proj onward ---
    cudaStreamWaitEvent(s2, e0, 0);
    tconv_kernel<<<dim3(128/32, DI/32), dim3(32,8), 0, s2>>>(x_proj_w,  wxp,  DI, 128);
    tconv_kernel<<<dim3(DI/32,  DR/32), dim3(32,8), 0, s2>>>(dt_proj_w, wdt,  DR, DI);
    tconv_kernel<<<dim3(DM/32,  DI/32), dim3(32,8), 0, s2>>>(out_proj_w, wout, DI, DM);
    cudaEventRecord(e_w, s2);

    // --- default: in_proj weight transpose ---
    tconv_kernel<<<dim3(4096/32, DM/32), dim3(32,8)>>>(in_proj_w, win, DM, 4096);
    cudaEventRecord(e_win, 0);

    // --- s1: z half of in_proj (cols 2048..4095) ---
    cudaStreamWaitEvent(s1, e_win, 0);
    mma_gemm<3><<<dim3(16, M_/128), 256, SMEM_P3, s1>>>(
        xh, win + (size_t)2048 * DM, nullptr, (float*)(xzh + 2048), DM, DM, 4096);
    cudaEventRecord(e_z, s1);

    // --- default: xi half of in_proj (cols 0..2047) ---
    cudaStreamWaitEvent(0, e_xh, 0);
    mma_gemm<3><<<dim3(16, M_/128), 256, SMEM_P3>>>(
        xh, win, nullptr, (float*)xzh, DM, DM, 4096);

    conv_silu_kernel<<<(M_*DI/2 + 255)/256, 256>>>(xzh, conv_w, conv_b, uh);

    cudaStreamWaitEvent(0, e_w, 0);
    mma_gemm_xp<<<dim3(2, M_/128), 256, SMEM_XP>>>(uh, wxp, dbc, dth, DI, 128);
    cudaEventRecord(e_xp, 0);

    // --- s2: dt_proj for d 1024..2047 (overlaps scan_d0) ---
    cudaStreamWaitEvent(s2, e_xp, 0);
    mma_gemm<1><<<dim3(8, M_/128), 256, SMEM_P3, s2>>>(
        dth, wdt + (size_t)1024 * DR, dt_proj_b + 1024, delta + 1024, DR, DR, DI);
    cudaEventRecord(e_dtp1, s2);

    // --- default: dt_proj for d 0..1023 ---
    mma_gemm<1><<<dim3(8, M_/128), 256, SMEM_P3>>>(
        dth, wdt, dt_proj_b, delta, DR, DR, DI);

    // --- default: scan d 0..1023 ---
    cudaStreamWaitEvent(0, e_z, 0);
    scan_kernel<<<dim3(128, B_), 256>>>(delta, uh, dbc, A_log, Dp, xzh, yh, 0);
    cudaEventRecord(e_s0, 0);

    // --- default: scan d 1024..2047 ---
    cudaStreamWaitEvent(0, e_dtp1, 0);
    scan_kernel<<<dim3(128, B_), 256>>>(delta, uh, dbc, A_log, Dp, xzh, yh, 1024);
    cudaEventRecord(e_s1, 0);

    // --- s1: out_proj K-split; k0 half overlaps scan_d1 ---
    cudaStreamWaitEvent(s1, e_w, 0);
    cudaStreamWaitEvent(s1, e_s0, 0);
    mma_gemm<0><<<dim3(DM/128, M_/128), 256, SMEM_P3, s1>>>(
        yh, wout, nullptr, out, 1024, DI, DM);
    cudaStreamWaitEvent(s1, e_s1, 0);
    mma_gemm<4><<<dim3(DM/128, M_/128), 256, SMEM_P3, s1>>>(
        yh + 1024, wout + 1024, nullptr, out, 1024, DI, DM);

    // --- s1: LayerNorm, then join ---
    ln_kernel<<<M_, 256, 0, s1>>>(out, ln_gamma, ln_beta);
    cudaEventRecord(e_done, s1);
    cudaStreamWaitEvent(0, e_done, 0);
}

// round 15
// speedup vs baseline: 1.0388x; 1.0388x over previous
#include <cuda_runtime.h>
#include <cuda_fp16.h>
#include <cstdint>

// ---------------- problem dims (fixed) ----------------
#define B_   4
#define L_   2048
#define DM   1024      // d_model
#define DI   2048      // d_inner
#define DS   32        // d_state
#define DR   64        // dt_rank
#define M_   (B_ * L_) // 8192 rows
#define LN_EPS 1e-5f

// ---------------- scratch (device globals; no allocs allowed) ----------------
__device__ __align__(256) float g_dbc[(size_t)M_ * 128];     // dt|B|C fp32
__device__ __align__(256) float g_delta[(size_t)M_ * DI];    // softplus fp32

// fp16 buffers
__device__ __align__(256) half g_xzh[(size_t)M_ * 2 * DI];   // xi | z fp16
__device__ __align__(256) half g_xh[(size_t)M_ * DM];
__device__ __align__(256) half g_uh[(size_t)M_ * DI];
__device__ __align__(256) half g_dth[(size_t)M_ * DR];
__device__ __align__(256) half g_yh[(size_t)M_ * DI];
// weights, converted + transposed to [N, K] fp16
__device__ __align__(256) half g_win[(size_t)4096 * DM];
__device__ __align__(256) half g_wxp[(size_t)128 * DI];
__device__ __align__(256) half g_wdt[(size_t)DI * DR];
__device__ __align__(256) half g_wout[(size_t)DM * DI];

// ---------------- helpers ----------------
__device__ __forceinline__ float siluf(float x) { return x / (1.f + expf(-x)); }
__device__ __forceinline__ float softplusf(float x) {
    return (x > 20.f) ? x : log1pf(expf(x));
}
__device__ __forceinline__ float ex2f(float x) {
    float y; asm("ex2.approx.ftz.f32 %0, %1;" : "=f"(y) : "f"(x)); return y;
}
__device__ __forceinline__ uint32_t smem_u32(const void* p) {
    return (uint32_t)__cvta_generic_to_shared(p);
}
__device__ __forceinline__ void cp16(uint32_t dst, const void* src) {
    asm volatile("cp.async.cg.shared.global [%0], [%1], 16;" :: "r"(dst), "l"(src));
}
__device__ __forceinline__ void ldm4(uint32_t* r, uint32_t addr) {
    asm volatile("ldmatrix.sync.aligned.m8n8.x4.shared.b16 {%0,%1,%2,%3}, [%4];"
                 : "=r"(r[0]), "=r"(r[1]), "=r"(r[2]), "=r"(r[3]) : "r"(addr));
}
__device__ __forceinline__ void mma16816(float* c, const uint32_t* a,
                                         uint32_t b0, uint32_t b1) {
    asm volatile(
        "mma.sync.aligned.m16n8k16.row.col.f32.f16.f16.f32 "
        "{%0,%1,%2,%3}, {%4,%5,%6,%7}, {%8,%9}, {%0,%1,%2,%3};"
        : "+f"(c[0]), "+f"(c[1]), "+f"(c[2]), "+f"(c[3])
        : "r"(a[0]), "r"(a[1]), "r"(a[2]), "r"(a[3]), "r"(b0), "r"(b1));
}

#define ROWB 80
#define APB  10240            // 128 rows * 80B
#define STGB 20480            // one stage: A(128x80) + B(128x80)

// ---------------- fp16 GEMM: 128x128 tile, 256 thr, 3-stage pipeline ----------------
// C[M,N] = Ah[M,K(lda)] x (Bh[N,K(lda)])^T, fp32 accum.
// ACT: 0 fp32 out, 1 softplus(+bias) fp32 out, 3 fp16 out.
template<int ACT>
__global__ void __launch_bounds__(256, 2)
mma_gemm(const half* __restrict__ Ah, const half* __restrict__ Bh,
         const float* __restrict__ bias, float* __restrict__ C,
         int K, int lda, int ldc) {
    extern __shared__ char smem[];
    const uint32_t sbase = smem_u32(smem);
    const int tid = threadIdx.x;
    const int lane = tid & 31, wid = tid >> 5;
    const int warp_m = wid >> 1, warp_n = wid & 1;
    const int bm = blockIdx.y * 128, bn = blockIdx.x * 128;

    float acc[2][8][4];
#pragma unroll
    for (int i = 0; i < 2; i++)
#pragma unroll
        for (int j = 0; j < 8; j++)
#pragma unroll
            for (int k = 0; k < 4; k++) acc[i][j][k] = 0.f;

    const int NK = K >> 5;

    auto stage_load = [&](int kt, uint32_t sb) {
        const int k0 = kt << 5;
#pragma unroll
        for (int ii = 0; ii < 2; ii++) {
            const int i = tid + ii * 256;
            const int r = i >> 2, c = i & 3;
            cp16(sb + (uint32_t)(r * ROWB + c * 16),
                 Ah + (size_t)(bm + r) * lda + k0 + c * 8);
        }
#pragma unroll
        for (int ii = 0; ii < 2; ii++) {
            const int i = tid + ii * 256;
            const int r = i >> 2, c = i & 3;
            cp16(sb + APB + (uint32_t)(r * ROWB + c * 16),
                 Bh + (size_t)(bn + r) * lda + k0 + c * 8);
        }
    };

    stage_load(0, sbase);
    asm volatile("cp.async.commit_group;" ::: "memory");
    stage_load(1, sbase + STGB);
    asm volatile("cp.async.commit_group;" ::: "memory");

    const int rsel = lane & 15, ksel = lane >> 4;
    int buf = 0, lbuf = 2;

    for (int kt = 0; kt < NK; kt++) {
        asm volatile("cp.async.wait_group 1;" ::: "memory");
        __syncthreads();
        if (kt + 2 < NK)
            stage_load(kt + 2, sbase + lbuf * STGB);
        asm volatile("cp.async.commit_group;" ::: "memory");

        const uint32_t sb = sbase + buf * STGB;
#pragma unroll
        for (int ks = 0; ks < 2; ks++) {
            uint32_t aH[2][4], bH[4][4];
            const uint32_t ko = (uint32_t)(ks * 2 + ksel) * 16;
#pragma unroll
            for (int i = 0; i < 2; i++) {
                const uint32_t off = (uint32_t)(warp_m * 32 + i * 16 + rsel) * ROWB + ko;
                ldm4(aH[i], sb + off);
            }
#pragma unroll
            for (int j = 0; j < 4; j++) {
                const uint32_t off = (uint32_t)(warp_n * 64 + j * 16 + rsel) * ROWB + ko;
                ldm4(bH[j], sb + APB + off);
            }
#pragma unroll
            for (int i = 0; i < 2; i++)
#pragma unroll
                for (int jj = 0; jj < 8; jj++) {
                    const int j = jj >> 1, s2 = jj & 1;
                    mma16816(acc[i][jj], aH[i], bH[j][s2], bH[j][s2 + 2]);
                }
        }
        buf = (buf == 2) ? 0 : buf + 1;
        lbuf = (lbuf == 2) ? 0 : lbuf + 1;
    }

    // epilogue
    const int g  = lane >> 2;
    const int tq = lane & 3;
#pragma unroll
    for (int i = 0; i < 2; i++) {
        const int row0 = bm + warp_m * 32 + i * 16 + g;
#pragma unroll
        for (int jj = 0; jj < 8; jj++) {
            const int col = bn + warp_n * 64 + jj * 8 + 2 * tq;
            float2 v0 = make_float2(acc[i][jj][0], acc[i][jj][1]);
            float2 v1 = make_float2(acc[i][jj][2], acc[i][jj][3]);
            if (ACT == 1) {
                const float bb0 = bias[col], bb1 = bias[col + 1];
                v0.x = softplusf(v0.x + bb0); v0.y = softplusf(v0.y + bb1);
                v1.x = softplusf(v1.x + bb0); v1.y = softplusf(v1.y + bb1);
            }
            if (ACT == 3) {
                half* C16 = (half*)C;
                *(__half2*)&C16[(size_t)row0 * ldc + col] =
                    __floats2half2_rn(v0.x, v0.y);
                *(__half2*)&C16[(size_t)(row0 + 8) * ldc + col] =
                    __floats2half2_rn(v1.x, v1.y);
            } else {
                *(float2*)&C[(size_t)row0 * ldc + col] = v0;
                *(float2*)&C[(size_t)(row0 + 8) * ldc + col] = v1;
            }
        }
    }
}

// ---------------- x_proj GEMM (BN=64, fused dt fp16 emit) ----------------
__global__ void __launch_bounds__(256)
mma_gemm_xp(const half* __restrict__ Ah, const half* __restrict__ Bh,
            float* __restrict__ C, half* __restrict__ dth,
            int K, int ldc) {
    constexpr int BPB = 64 * ROWB;
    constexpr int STG = APB + BPB;

    extern __shared__ char smem[];
    const uint32_t sbase = smem_u32(smem);
    const int tid = threadIdx.x;
    const int lane = tid & 31, wid = tid >> 5;
    const int warp_m = wid >> 1, warp_n = wid & 1;
    const int bm = blockIdx.y * 128, bn = blockIdx.x * 64;

    float acc[2][4][4];
#pragma unroll
    for (int i = 0; i < 2; i++)
#pragma unroll
        for (int t = 0; t < 4; t++)
#pragma unroll
            for (int k = 0; k < 4; k++) acc[i][t][k] = 0.f;

    const int NK = K >> 5;

    auto stage_load = [&](int kt, uint32_t sb) {
        const int k0 = kt << 5;
#pragma unroll
        for (int ii = 0; ii < 2; ii++) {
            const int i = tid + ii * 256;
            const int r = i >> 2, c = i & 3;
            cp16(sb + (uint32_t)(r * ROWB + c * 16),
                 Ah + (size_t)(bm + r) * K + k0 + c * 8);
        }
        {
            const int r = tid >> 2, c = tid & 3;
            if (r < 64)
                cp16(sb + APB + (uint32_t)(r * ROWB + c * 16),
                     Bh + (size_t)(bn + r) * K + k0 + c * 8);
        }
    };

    stage_load(0, sbase);
    asm volatile("cp.async.commit_group;" ::: "memory");

    const int rsel = lane & 15, ksel = lane >> 4;

    for (int kt = 0; kt < NK; kt++) {
        if (kt + 1 < NK)
            stage_load(kt + 1, sbase + ((kt + 1) & 1) * STG);
        asm volatile("cp.async.commit_group;" ::: "memory");
        asm volatile("cp.async.wait_group 1;" ::: "memory");
        __syncthreads();

        const uint32_t sb = sbase + (kt & 1) * STG;
#pragma unroll
        for (int ks = 0; ks < 2; ks++) {
            uint32_t aH[2][4], bH[2][4];
            const uint32_t ko = (uint32_t)(ks * 2 + ksel) * 16;
#pragma unroll
            for (int i = 0; i < 2; i++) {
                const uint32_t off = (uint32_t)(warp_m * 32 + i * 16 + rsel) * ROWB + ko;
                ldm4(aH[i], sb + off);
            }
#pragma unroll
            for (int j = 0; j < 2; j++) {
                const uint32_t off = (uint32_t)(warp_n * 32 + j * 16 + rsel) * ROWB + ko;
                ldm4(bH[j], sb + APB + off);
            }
#pragma unroll
            for (int i = 0; i < 2; i++)
#pragma unroll
                for (int t = 0; t < 4; t++) {
                    const int j = t >> 1, s2 = t & 1;
                    mma16816(acc[i][t], aH[i], bH[j][s2], bH[j][s2 + 2]);
                }
        }
        __syncthreads();
    }

    const int g  = lane >> 2;
    const int tq = lane & 3;
#pragma unroll
    for (int i = 0; i < 2; i++) {
        const int row0 = bm + warp_m * 32 + i * 16 + g;
#pragma unroll
        for (int t = 0; t < 4; t++) {
            const int col = bn + warp_n * 32 + t * 8 + 2 * tq;
            float2 v0 = make_float2(acc[i][t][0], acc[i][t][1]);
            float2 v1 = make_float2(acc[i][t][2], acc[i][t][3]);
            *(float2*)&C[(size_t)row0 * ldc + col] = v0;
            *(float2*)&C[(size_t)(row0 + 8) * ldc + col] = v1;
            if (blockIdx.x == 0) {   // cols 0..63 = dt
                dth[(size_t)row0 * DR + col]           = __float2half(v0.x);
                dth[(size_t)row0 * DR + col + 1]       = __float2half(v0.y);
                dth[(size_t)(row0 + 8) * DR + col]     = __float2half(v1.x);
                dth[(size_t)(row0 + 8) * DR + col + 1] = __float2half(v1.y);
            }
        }
    }
}

// ---------------- producers: fp16 convert ----------------
__global__ void conv16_kernel(const float2* __restrict__ src,
                              uint32_t* __restrict__ hi, int n2) {
    int i = blockIdx.x * blockDim.x + threadIdx.x;
    if (i >= n2) return;
    float2 f = src[i];
    half h0 = __float2half(f.x), h1 = __float2half(f.y);
    hi[i] = (uint32_t)__half_as_ushort(h0) | ((uint32_t)__half_as_ushort(h1) << 16);
}

// weights: src [K,N] fp32 -> dst [N,K] fp16
__global__ void tconv_kernel(const float* __restrict__ src,
                             half* __restrict__ dst, int K, int N) {
    __shared__ float t[32][33];
    const int k0 = blockIdx.y * 32, n0 = blockIdx.x * 32;
    const int tx = threadIdx.x, ty = threadIdx.y;
#pragma unroll
    for (int i = 0; i < 32; i += 8)
        t[ty + i][tx] = src[(size_t)(k0 + ty + i) * N + n0 + tx];
    __syncthreads();
#pragma unroll
    for (int i = 0; i < 32; i += 8)
        dst[(size_t)(n0 + ty + i) * K + k0 + tx] = __float2half(t[tx][ty + i]);
}

// ---------------- causal conv1d (D_CONV=4) + silu, half2 vectorized ----------------
__global__ void conv_silu_kernel(const half* __restrict__ xzh,
                                 const float* __restrict__ cw,
                                 const float* __restrict__ cb,
                                 half* __restrict__ uh) {
    int idx = blockIdx.x * blockDim.x + threadIdx.x;   // over M_*DI/2
    if (idx >= M_ * DI / 2) return;
    const int d2 = idx & (DI / 2 - 1);                 // half2 col
    const int t  = (idx >> 10) & (L_ - 1);
    const int b  = idx >> 21;
    const int d  = d2 * 2;

    const float4 w0 = ((const float4*)cw)[d];
    const float4 w1 = ((const float4*)cw)[d + 1];
    float a0 = cb[d], a1 = cb[d + 1];

    const __half2* p = (const __half2*)xzh;
    const size_t rb = (size_t)(b * L_) * DI + d2;

    if (t >= 3) {
        float2 f;
        f = __half22float2(p[rb + (size_t)(t - 3) * DI]);
        a0 = fmaf(f.x, w0.x, a0); a1 = fmaf(f.y, w1.x, a1);
        f = __half22float2(p[rb + (size_t)(t - 2) * DI]);
        a0 = fmaf(f.x, w0.y, a0); a1 = fmaf(f.y, w1.y, a1);
        f = __half22float2(p[rb + (size_t)(t - 1) * DI]);
        a0 = fmaf(f.x, w0.z, a0); a1 = fmaf(f.y, w1.z, a1);
        f = __half22float2(p[rb + (size_t)(t    ) * DI]);
        a0 = fmaf(f.x, w0.w, a0); a1 = fmaf(f.y, w1.w, a1);
    } else {
        const float wk0[4] = {w0.x, w0.y, w0.z, w0.w};
        const float wk1[4] = {w1.x, w1.y, w1.z, w1.w};
#pragma unroll
        for (int k = 0; k < 4; k++) {
            int tt = t + k - 3;
            if (tt >= 0) {
                float2 f = __half22float2(p[rb + (size_t)tt * DI]);
                a0 = fmaf(f.x, wk0[k], a0); a1 = fmaf(f.y, wk1[k], a1);
            }
        }
    }
    ((__half2*)uh)[(size_t)(b * L_ + t) * (DI / 2) + d2] =
        __floats2half2_rn(siluf(a0), siluf(a1));
}

// ---------------- selective scan + gating (64-step tiles, 16-step reduce) ----------------
// d-range split: handles channels [doff, doff + gridDim.x*8)
__global__ void __launch_bounds__(256)
scan_kernel(const float* __restrict__ delta,
            const half* __restrict__ uh,
            const float* __restrict__ dbc,
            const float* __restrict__ A_log,
            const float* __restrict__ Dp,
            const half* __restrict__ xzh,
            half* __restrict__ yh, int doff) {
    const int lane = threadIdx.x & 31;
    const int w    = threadIdx.x >> 5;            // 0..7
    const int d0   = doff + blockIdx.x * 8;
    const int b    = blockIdx.y;

    __shared__ float2 sBC[64][32];                // [t][s] = (B, C)
    __shared__ float2 sDP[64][8];                 // [t][w] = (delta, delta*u)
    __shared__ float  sh[64][9];                  // output transpose, padded

    const float A2 = -expf(A_log[(d0 + w) * DS + lane]) * 1.4426950408889634f;

    const int lt = threadIdx.x >> 3;              // 0..31
    const int lq = threadIdx.x & 7;               // 0..7
    const float Dv = Dp[d0 + lq];

    float h = 0.f;

    for (int t0 = 0; t0 < L_; t0 += 64) {
        float uu[2], zz[2];
#pragma unroll
        for (int rr = 0; rr < 2; rr++) {
            const int row = lt + rr * 32;
            const size_t lrow = (size_t)(b * L_ + t0 + row);
            const float4* src = (const float4*)(dbc + lrow * 128 + 64);
            const float4 B4 = src[lq];
            const float4 C4 = src[lq + 8];
            sBC[row][lq * 4 + 0] = make_float2(B4.x, C4.x);
            sBC[row][lq * 4 + 1] = make_float2(B4.y, C4.y);
            sBC[row][lq * 4 + 2] = make_float2(B4.z, C4.z);
            sBC[row][lq * 4 + 3] = make_float2(B4.w, C4.w);
            const float dl = delta[lrow * DI + d0 + lq];
            uu[rr] = __half2float(uh[lrow * DI + d0 + lq]);
            zz[rr] = __half2float(xzh[lrow * (size_t)(2 * DI) + DI + d0 + lq]);
            sDP[row][lq] = make_float2(dl, dl * uu[rr]);
        }
        __syncthreads();

#pragma unroll
        for (int ch = 0; ch < 4; ch++) {
            float v[16];
#pragma unroll
            for (int ti = 0; ti < 16; ti++) {
                const int tt = ch * 16 + ti;
                const float2 dp = sDP[tt][w];
                const float2 bc = sBC[tt][lane];
                h = fmaf(ex2f(dp.x * A2), h, dp.y * bc.x);
                v[ti] = h * bc.y;
            }
            const bool hi8 = (lane & 8) != 0;
#pragma unroll
            for (int j = 0; j < 8; j++) {
                float send = hi8 ? v[j] : v[j + 8];
                float r = __shfl_xor_sync(0xffffffffu, send, 8);
                v[j] = (hi8 ? v[j + 8] : v[j]) + r;
            }
            const bool hi4 = (lane & 4) != 0;
#pragma unroll
            for (int j = 0; j < 4; j++) {
                float send = hi4 ? v[j] : v[j + 4];
                float r = __shfl_xor_sync(0xffffffffu, send, 4);
                v[j] = (hi4 ? v[j + 4] : v[j]) + r;
            }
            const bool hi2 = (lane & 2) != 0;
#pragma unroll
            for (int j = 0; j < 2; j++) {
                float send = hi2 ? v[j] : v[j + 2];
                float r = __shfl_xor_sync(0xffffffffu, send, 2);
                v[j] = (hi2 ? v[j + 2] : v[j]) + r;
            }
            const bool hi1 = (lane & 1) != 0;
            {
                float send = hi1 ? v[0] : v[1];
                float r = __shfl_xor_sync(0xffffffffu, send, 1);
                v[0] = (hi1 ? v[1] : v[0]) + r;
            }
            v[0] += __shfl_xor_sync(0xffffffffu, v[0], 16);
            if (lane < 16) sh[ch * 16 + lane][w] = v[0];
        }
        __syncthreads();

#pragma unroll
        for (int rr = 0; rr < 2; rr++) {
            const int row = lt + rr * 32;
            const size_t lrow = (size_t)(b * L_ + t0 + row);
            const float yv = sh[row][lq];
            const float yf = (yv + uu[rr] * Dv) * siluf(zz[rr]);
            yh[lrow * DI + d0 + lq] = __float2half(yf);
        }
        __syncthreads();
    }
}

// ---------------- in-place LayerNorm (row = 1024) ----------------
__global__ void ln_kernel(float* __restrict__ out,
                          const float* __restrict__ gamma,
                          const float* __restrict__ beta) {
    const int row = blockIdx.x;
    float4* p = (float4*)(out + (size_t)row * DM);
    const int i = threadIdx.x;

    float4 x = p[i];
    float s = x.x + x.y + x.z + x.w;
    float q = x.x * x.x + x.y * x.y + x.z * x.z + x.w * x.w;
#pragma unroll
    for (int o = 16; o; o >>= 1) {
        s += __shfl_xor_sync(0xffffffffu, s, o);
        q += __shfl_xor_sync(0xffffffffu, q, o);
    }
    __shared__ float rs[8], rq[8];
    if ((i & 31) == 0) { rs[i >> 5] = s; rq[i >> 5] = q; }
    __syncthreads();
    s = 0.f; q = 0.f;
#pragma unroll
    for (int k = 0; k < 8; k++) { s += rs[k]; q += rq[k]; }

    const float mu  = s * (1.f / DM);
    const float var = q * (1.f / DM) - mu * mu;
    const float inv = rsqrtf(var + LN_EPS);

    const float4 gg = ((const float4*)gamma)[i];
    const float4 bb = ((const float4*)beta)[i];
    x.x = (x.x - mu) * inv * gg.x + bb.x;
    x.y = (x.y - mu) * inv * gg.y + bb.y;
    x.z = (x.z - mu) * inv * gg.z + bb.z;
    x.w = (x.w - mu) * inv * gg.w + bb.w;
    p[i] = x;
}

// ---------------- launch ----------------
extern "C" void kernel_launch(void* const* d_in, const int* in_sizes, int n_in,
                              void* d_out, int out_size) {
    (void)in_sizes; (void)n_in; (void)out_size;
    const float* x         = (const float*)d_in[0];
    const float* in_proj_w = (const float*)d_in[1];
    const float* conv_w    = (const float*)d_in[2];
    const float* conv_b    = (const float*)d_in[3];
    const float* x_proj_w  = (const float*)d_in[4];
    const float* dt_proj_w = (const float*)d_in[5];
    const float* dt_proj_b = (const float*)d_in[6];
    const float* A_log     = (const float*)d_in[7];
    const float* Dp        = (const float*)d_in[8];
    const float* out_proj_w= (const float*)d_in[9];
    const float* ln_gamma  = (const float*)d_in[10];
    const float* ln_beta   = (const float*)d_in[11];
    float* out = (float*)d_out;

    float *dbc, *delta;
    half *xzh, *xh, *uh, *dth, *yh;
    half *win, *wxp, *wdt, *wout;
    cudaGetSymbolAddress((void**)&dbc,   g_dbc);
    cudaGetSymbolAddress((void**)&delta, g_delta);
    cudaGetSymbolAddress((void**)&xzh,   g_xzh);
    cudaGetSymbolAddress((void**)&xh,    g_xh);
    cudaGetSymbolAddress((void**)&uh,    g_uh);
    cudaGetSymbolAddress((void**)&dth,   g_dth);
    cudaGetSymbolAddress((void**)&yh,    g_yh);
    cudaGetSymbolAddress((void**)&win,   g_win);
    cudaGetSymbolAddress((void**)&wxp,   g_wxp);
    cudaGetSymbolAddress((void**)&wdt,   g_wdt);
    cudaGetSymbolAddress((void**)&wout,  g_wout);

    constexpr int SMEM_P3 = 3 * STGB;          // 61440
    constexpr int STG_XP  = APB + 64 * ROWB;   // 15360
    constexpr int SMEM_XP = 2 * STG_XP;        // 30720
    cudaFuncSetAttribute(mma_gemm<0>, cudaFuncAttributeMaxDynamicSharedMemorySize, SMEM_P3);
    cudaFuncSetAttribute(mma_gemm<1>, cudaFuncAttributeMaxDynamicSharedMemorySize, SMEM_P3);
    cudaFuncSetAttribute(mma_gemm<3>, cudaFuncAttributeMaxDynamicSharedMemorySize, SMEM_P3);
    cudaFuncSetAttribute(mma_gemm_xp, cudaFuncAttributeMaxDynamicSharedMemorySize, SMEM_XP);

    // streams/events (created once; handles only)
    static cudaStream_t s1 = nullptr, s2 = nullptr;
    static cudaEvent_t e0 = nullptr, e_win = nullptr, e_xh = nullptr,
                       e_w = nullptr, e_z = nullptr, e_xp = nullptr,
                       e_s1 = nullptr;
    if (s1 == nullptr) {
        cudaStreamCreateWithFlags(&s1, cudaStreamNonBlocking);
        cudaStreamCreateWithFlags(&s2, cudaStreamNonBlocking);
        cudaEventCreateWithFlags(&e0,    cudaEventDisableTiming);
        cudaEventCreateWithFlags(&e_win, cudaEventDisableTiming);
        cudaEventCreateWithFlags(&e_xh,  cudaEventDisableTiming);
        cudaEventCreateWithFlags(&e_w,   cudaEventDisableTiming);
        cudaEventCreateWithFlags(&e_z,   cudaEventDisableTiming);
        cudaEventCreateWithFlags(&e_xp,  cudaEventDisableTiming);
        cudaEventCreateWithFlags(&e_s1,  cudaEventDisableTiming);
    }

    // fork point
    cudaEventRecord(e0, 0);

    // --- s1: x convert, then (after win) the z-half GEMM ---
    cudaStreamWaitEvent(s1, e0, 0);
    conv16_kernel<<<(M_*DM/2 + 255)/256, 256, 0, s1>>>(
        (const float2*)x, (uint32_t*)xh, M_*DM/2);
    cudaEventRecord(e_xh, s1);

    // --- s2: weight transposes needed from x_proj onward ---
    cudaStreamWaitEvent(s2, e0, 0);
    tconv_kernel<<<dim3(128/32, DI/32), dim3(32,8), 0, s2>>>(x_proj_w,  wxp,  DI, 128);
    tconv_kernel<<<dim3(DI/32,  DR/32), dim3(32,8), 0, s2>>>(dt_proj_w, wdt,  DR, DI);
    tconv_kernel<<<dim3(DM/32,  DI/32), dim3(32,8), 0, s2>>>(out_proj_w, wout, DI, DM);
    cudaEventRecord(e_w, s2);

    // --- default: in_proj weight transpose ---
    tconv_kernel<<<dim3(4096/32, DM/32), dim3(32,8)>>>(in_proj_w, win, DM, 4096);
    cudaEventRecord(e_win, 0);

    // --- s1: z half of in_proj (cols 2048..4095) ---
    cudaStreamWaitEvent(s1, e_win, 0);
    mma_gemm<3><<<dim3(16, M_/128), 256, SMEM_P3, s1>>>(
        xh, win + (size_t)2048 * DM, nullptr, (float*)(xzh + 2048), DM, DM, 4096);
    cudaEventRecord(e_z, s1);

    // --- default: xi half of in_proj (cols 0..2047) ---
    cudaStreamWaitEvent(0, e_xh, 0);
    mma_gemm<3><<<dim3(16, M_/128), 256, SMEM_P3>>>(
        xh, win, nullptr, (float*)xzh, DM, DM, 4096);

    conv_silu_kernel<<<(M_*DI/2 + 255)/256, 256>>>(xzh, conv_w, conv_b, uh);

    cudaStreamWaitEvent(0, e_w, 0);
    mma_gemm_xp<<<dim3(2, M_/128), 256, SMEM_XP>>>(uh, wxp, dbc, dth, DI, 128);
    cudaEventRecord(e_xp, 0);

    // --- s2: dt_proj d1 -> scan d1, concurrent with default's d0 chain ---
    cudaStreamWaitEvent(s2, e_xp, 0);
    cudaStreamWaitEvent(s2, e_z, 0);
    mma_gemm<1><<<dim3(8, M_/128), 256, SMEM_P3, s2>>>(
        dth, wdt + (size_t)1024 * DR, dt_proj_b + 1024, delta + 1024, DR, DR, DI);
    scan_kernel<<<dim3(128, B_), 256, 0, s2>>>(delta, uh, dbc, A_log, Dp, xzh, yh, 1024);
    cudaEventRecord(e_s1, s2);

    // --- default: dt_proj d0 -> scan d0 ---
    mma_gemm<1><<<dim3(8, M_/128), 256, SMEM_P3>>>(
        dth, wdt, dt_proj_b, delta, DR, DR, DI);
    cudaStreamWaitEvent(0, e_z, 0);
    scan_kernel<<<dim3(128, B_), 256>>>(delta, uh, dbc, A_log, Dp, xzh, yh, 0);

    // --- default: out_proj (whole), after both scan halves ---
    cudaStreamWaitEvent(0, e_s1, 0);
    mma_gemm<0><<<dim3(DM/128, M_/128), 256, SMEM_P3>>>(
        yh, wout, nullptr, out, DI, DI, DM);

    ln_kernel<<<M_, 256>>>(out, ln_gamma, ln_beta);
}

// round 16
// speedup vs baseline: 1.1005x; 1.0593x over previous
#include <cuda_runtime.h>
#include <cuda_fp16.h>
#include <cstdint>

// ---------------- problem dims (fixed) ----------------
#define B_   4
#define L_   2048
#define DM   1024      // d_model
#define DI   2048      // d_inner
#define DS   32        // d_state
#define DR   64        // dt_rank
#define M_   (B_ * L_) // 8192 rows
#define LN_EPS 1e-5f

// ---------------- scratch (device globals; no allocs allowed) ----------------
__device__ __align__(256) float g_dbc[(size_t)M_ * 128];     // dt|B|C fp32
__device__ __align__(256) float g_delta[(size_t)M_ * DI];    // softplus fp32

// fp16 buffers
__device__ __align__(256) half g_xzh[(size_t)M_ * 2 * DI];   // xi | z fp16
__device__ __align__(256) half g_xh[(size_t)M_ * DM];
__device__ __align__(256) half g_uh[(size_t)M_ * DI];
__device__ __align__(256) half g_dth[(size_t)M_ * DR];
__device__ __align__(256) half g_yh[(size_t)M_ * DI];
// weights, converted + transposed to [N, K] fp16
__device__ __align__(256) half g_win[(size_t)4096 * DM];
__device__ __align__(256) half g_wxp[(size_t)128 * DI];
__device__ __align__(256) half g_wdt[(size_t)DI * DR];
__device__ __align__(256) half g_wout[(size_t)DM * DI];

// ---------------- helpers ----------------
__device__ __forceinline__ float siluf(float x) { return x / (1.f + expf(-x)); }
__device__ __forceinline__ float softplusf(float x) {
    return (x > 20.f) ? x : log1pf(expf(x));
}
__device__ __forceinline__ float ex2f(float x) {
    float y; asm("ex2.approx.ftz.f32 %0, %1;" : "=f"(y) : "f"(x)); return y;
}
__device__ __forceinline__ uint32_t smem_u32(const void* p) {
    return (uint32_t)__cvta_generic_to_shared(p);
}
__device__ __forceinline__ void cp16(uint32_t dst, const void* src) {
    asm volatile("cp.async.cg.shared.global [%0], [%1], 16;" :: "r"(dst), "l"(src));
}
__device__ __forceinline__ void ldm4(uint32_t* r, uint32_t addr) {
    asm volatile("ldmatrix.sync.aligned.m8n8.x4.shared.b16 {%0,%1,%2,%3}, [%4];"
                 : "=r"(r[0]), "=r"(r[1]), "=r"(r[2]), "=r"(r[3]) : "r"(addr));
}
__device__ __forceinline__ void mma16816(float* c, const uint32_t* a,
                                         uint32_t b0, uint32_t b1) {
    asm volatile(
        "mma.sync.aligned.m16n8k16.row.col.f32.f16.f16.f32 "
        "{%0,%1,%2,%3}, {%4,%5,%6,%7}, {%8,%9}, {%0,%1,%2,%3};"
        : "+f"(c[0]), "+f"(c[1]), "+f"(c[2]), "+f"(c[3])
        : "r"(a[0]), "r"(a[1]), "r"(a[2]), "r"(a[3]), "r"(b0), "r"(b1));
}

#define ROWB 80
#define APB  10240            // 128 rows * 80B
#define STGB 20480            // one stage: A(128x80) + B(128x80)

// ---------------- fp16 GEMM: 128x128 tile, 256 thr, 3-stage pipeline ----------------
// ACT: 0 fp32 out, 1 softplus(+bias) fp32 out, 3 fp16 out.
template<int ACT>
__global__ void __launch_bounds__(256, 2)
mma_gemm(const half* __restrict__ Ah, const half* __restrict__ Bh,
         const float* __restrict__ bias, float* __restrict__ C,
         int K, int ldc) {
    extern __shared__ char smem[];
    const uint32_t sbase = smem_u32(smem);
    const int tid = threadIdx.x;
    const int lane = tid & 31, wid = tid >> 5;
    const int warp_m = wid >> 1, warp_n = wid & 1;
    const int bm = blockIdx.y * 128, bn = blockIdx.x * 128;

    float acc[2][8][4];
#pragma unroll
    for (int i = 0; i < 2; i++)
#pragma unroll
        for (int j = 0; j < 8; j++)
#pragma unroll
            for (int k = 0; k < 4; k++) acc[i][j][k] = 0.f;

    const int NK = K >> 5;

    auto stage_load = [&](int kt, uint32_t sb) {
        const int k0 = kt << 5;
#pragma unroll
        for (int ii = 0; ii < 2; ii++) {
            const int i = tid + ii * 256;
            const int r = i >> 2, c = i & 3;
            cp16(sb + (uint32_t)(r * ROWB + c * 16),
                 Ah + (size_t)(bm + r) * K + k0 + c * 8);
        }
#pragma unroll
        for (int ii = 0; ii < 2; ii++) {
            const int i = tid + ii * 256;
            const int r = i >> 2, c = i & 3;
            cp16(sb + APB + (uint32_t)(r * ROWB + c * 16),
                 Bh + (size_t)(bn + r) * K + k0 + c * 8);
        }
    };

    stage_load(0, sbase);
    asm volatile("cp.async.commit_group;" ::: "memory");
    stage_load(1, sbase + STGB);
    asm volatile("cp.async.commit_group;" ::: "memory");

    const int rsel = lane & 15, ksel = lane >> 4;
    int buf = 0, lbuf = 2;

    for (int kt = 0; kt < NK; kt++) {
        asm volatile("cp.async.wait_group 1;" ::: "memory");
        __syncthreads();
        if (kt + 2 < NK)
            stage_load(kt + 2, sbase + lbuf * STGB);
        asm volatile("cp.async.commit_group;" ::: "memory");

        const uint32_t sb = sbase + buf * STGB;
#pragma unroll
        for (int ks = 0; ks < 2; ks++) {
            uint32_t aH[2][4], bH[4][4];
            const uint32_t ko = (uint32_t)(ks * 2 + ksel) * 16;
#pragma unroll
            for (int i = 0; i < 2; i++) {
                const uint32_t off = (uint32_t)(warp_m * 32 + i * 16 + rsel) * ROWB + ko;
                ldm4(aH[i], sb + off);
            }
#pragma unroll
            for (int j = 0; j < 4; j++) {
                const uint32_t off = (uint32_t)(warp_n * 64 + j * 16 + rsel) * ROWB + ko;
                ldm4(bH[j], sb + APB + off);
            }
#pragma unroll
            for (int i = 0; i < 2; i++)
#pragma unroll
                for (int jj = 0; jj < 8; jj++) {
                    const int j = jj >> 1, s2 = jj & 1;
                    mma16816(acc[i][jj], aH[i], bH[j][s2], bH[j][s2 + 2]);
                }
        }
        buf = (buf == 2) ? 0 : buf + 1;
        lbuf = (lbuf == 2) ? 0 : lbuf + 1;
    }

    // epilogue
    const int g  = lane >> 2;
    const int tq = lane & 3;
#pragma unroll
    for (int i = 0; i < 2; i++) {
        const int row0 = bm + warp_m * 32 + i * 16 + g;
#pragma unroll
        for (int jj = 0; jj < 8; jj++) {
            const int col = bn + warp_n * 64 + jj * 8 + 2 * tq;
            float2 v0 = make_float2(acc[i][jj][0], acc[i][jj][1]);
            float2 v1 = make_float2(acc[i][jj][2], acc[i][jj][3]);
            if (ACT == 1) {
                const float bb0 = bias[col], bb1 = bias[col + 1];
                v0.x = softplusf(v0.x + bb0); v0.y = softplusf(v0.y + bb1);
                v1.x = softplusf(v1.x + bb0); v1.y = softplusf(v1.y + bb1);
            }
            if (ACT == 3) {
                half* C16 = (half*)C;
                *(__half2*)&C16[(size_t)row0 * ldc + col] =
                    __floats2half2_rn(v0.x, v0.y);
                *(__half2*)&C16[(size_t)(row0 + 8) * ldc + col] =
                    __floats2half2_rn(v1.x, v1.y);
            } else {
                *(float2*)&C[(size_t)row0 * ldc + col] = v0;
                *(float2*)&C[(size_t)(row0 + 8) * ldc + col] = v1;
            }
        }
    }
}

// ---------------- x_proj GEMM (BN=64, fused dt fp16 emit) ----------------
__global__ void __launch_bounds__(256)
mma_gemm_xp(const half* __restrict__ Ah, const half* __restrict__ Bh,
            float* __restrict__ C, half* __restrict__ dth,
            int K, int ldc) {
    constexpr int BPB = 64 * ROWB;
    constexpr int STG = APB + BPB;

    extern __shared__ char smem[];
    const uint32_t sbase = smem_u32(smem);
    const int tid = threadIdx.x;
    const int lane = tid & 31, wid = tid >> 5;
    const int warp_m = wid >> 1, warp_n = wid & 1;
    const int bm = blockIdx.y * 128, bn = blockIdx.x * 64;

    float acc[2][4][4];
#pragma unroll
    for (int i = 0; i < 2; i++)
#pragma unroll
        for (int t = 0; t < 4; t++)
#pragma unroll
            for (int k = 0; k < 4; k++) acc[i][t][k] = 0.f;

    const int NK = K >> 5;

    auto stage_load = [&](int kt, uint32_t sb) {
        const int k0 = kt << 5;
#pragma unroll
        for (int ii = 0; ii < 2; ii++) {
            const int i = tid + ii * 256;
            const int r = i >> 2, c = i & 3;
            cp16(sb + (uint32_t)(r * ROWB + c * 16),
                 Ah + (size_t)(bm + r) * K + k0 + c * 8);
        }
        {
            const int r = tid >> 2, c = tid & 3;
            if (r < 64)
                cp16(sb + APB + (uint32_t)(r * ROWB + c * 16),
                     Bh + (size_t)(bn + r) * K + k0 + c * 8);
        }
    };

    stage_load(0, sbase);
    asm volatile("cp.async.commit_group;" ::: "memory");

    const int rsel = lane & 15, ksel = lane >> 4;

    for (int kt = 0; kt < NK; kt++) {
        if (kt + 1 < NK)
            stage_load(kt + 1, sbase + ((kt + 1) & 1) * STG);
        asm volatile("cp.async.commit_group;" ::: "memory");
        asm volatile("cp.async.wait_group 1;" ::: "memory");
        __syncthreads();

        const uint32_t sb = sbase + (kt & 1) * STG;
#pragma unroll
        for (int ks = 0; ks < 2; ks++) {
            uint32_t aH[2][4], bH[2][4];
            const uint32_t ko = (uint32_t)(ks * 2 + ksel) * 16;
#pragma unroll
            for (int i = 0; i < 2; i++) {
                const uint32_t off = (uint32_t)(warp_m * 32 + i * 16 + rsel) * ROWB + ko;
                ldm4(aH[i], sb + off);
            }
#pragma unroll
            for (int j = 0; j < 2; j++) {
                const uint32_t off = (uint32_t)(warp_n * 32 + j * 16 + rsel) * ROWB + ko;
                ldm4(bH[j], sb + APB + off);
            }
#pragma unroll
            for (int i = 0; i < 2; i++)
#pragma unroll
                for (int t = 0; t < 4; t++) {
                    const int j = t >> 1, s2 = t & 1;
                    mma16816(acc[i][t], aH[i], bH[j][s2], bH[j][s2 + 2]);
                }
        }
        __syncthreads();
    }

    const int g  = lane >> 2;
    const int tq = lane & 3;
#pragma unroll
    for (int i = 0; i < 2; i++) {
        const int row0 = bm + warp_m * 32 + i * 16 + g;
#pragma unroll
        for (int t = 0; t < 4; t++) {
            const int col = bn + warp_n * 32 + t * 8 + 2 * tq;
            float2 v0 = make_float2(acc[i][t][0], acc[i][t][1]);
            float2 v1 = make_float2(acc[i][t][2], acc[i][t][3]);
            *(float2*)&C[(size_t)row0 * ldc + col] = v0;
            *(float2*)&C[(size_t)(row0 + 8) * ldc + col] = v1;
            if (blockIdx.x == 0) {   // cols 0..63 = dt
                dth[(size_t)row0 * DR + col]           = __float2half(v0.x);
                dth[(size_t)row0 * DR + col + 1]       = __float2half(v0.y);
                dth[(size_t)(row0 + 8) * DR + col]     = __float2half(v1.x);
                dth[(size_t)(row0 + 8) * DR + col + 1] = __float2half(v1.y);
            }
        }
    }
}

// ---------------- producers: fp16 convert ----------------
__global__ void conv16_kernel(const float2* __restrict__ src,
                              uint32_t* __restrict__ hi, int n2) {
    int i = blockIdx.x * blockDim.x + threadIdx.x;
    if (i >= n2) return;
    float2 f = src[i];
    half h0 = __float2half(f.x), h1 = __float2half(f.y);
    hi[i] = (uint32_t)__half_as_ushort(h0) | ((uint32_t)__half_as_ushort(h1) << 16);
}

// weights: src [K,N] fp32 -> dst [N,K] fp16
__global__ void tconv_kernel(const float* __restrict__ src,
                             half* __restrict__ dst, int K, int N) {
    __shared__ float t[32][33];
    const int k0 = blockIdx.y * 32, n0 = blockIdx.x * 32;
    const int tx = threadIdx.x, ty = threadIdx.y;
#pragma unroll
    for (int i = 0; i < 32; i += 8)
        t[ty + i][tx] = src[(size_t)(k0 + ty + i) * N + n0 + tx];
    __syncthreads();
#pragma unroll
    for (int i = 0; i < 32; i += 8)
        dst[(size_t)(n0 + ty + i) * K + k0 + tx] = __float2half(t[tx][ty + i]);
}

// ---------------- causal conv1d (D_CONV=4) + silu, half2 vectorized ----------------
__global__ void conv_silu_kernel(const half* __restrict__ xzh,
                                 const float* __restrict__ cw,
                                 const float* __restrict__ cb,
                                 half* __restrict__ uh) {
    int idx = blockIdx.x * blockDim.x + threadIdx.x;   // over M_*DI/2
    if (idx >= M_ * DI / 2) return;
    const int d2 = idx & (DI / 2 - 1);                 // half2 col
    const int t  = (idx >> 10) & (L_ - 1);
    const int b  = idx >> 21;
    const int d  = d2 * 2;

    const float4 w0 = ((const float4*)cw)[d];
    const float4 w1 = ((const float4*)cw)[d + 1];
    float a0 = cb[d], a1 = cb[d + 1];

    const __half2* p = (const __half2*)xzh;
    const size_t rb = (size_t)(b * L_) * DI + d2;

    if (t >= 3) {
        float2 f;
        f = __half22float2(p[rb + (size_t)(t - 3) * DI]);
        a0 = fmaf(f.x, w0.x, a0); a1 = fmaf(f.y, w1.x, a1);
        f = __half22float2(p[rb + (size_t)(t - 2) * DI]);
        a0 = fmaf(f.x, w0.y, a0); a1 = fmaf(f.y, w1.y, a1);
        f = __half22float2(p[rb + (size_t)(t - 1) * DI]);
        a0 = fmaf(f.x, w0.z, a0); a1 = fmaf(f.y, w1.z, a1);
        f = __half22float2(p[rb + (size_t)(t    ) * DI]);
        a0 = fmaf(f.x, w0.w, a0); a1 = fmaf(f.y, w1.w, a1);
    } else {
        const float wk0[4] = {w0.x, w0.y, w0.z, w0.w};
        const float wk1[4] = {w1.x, w1.y, w1.z, w1.w};
#pragma unroll
        for (int k = 0; k < 4; k++) {
            int tt = t + k - 3;
            if (tt >= 0) {
                float2 f = __half22float2(p[rb + (size_t)tt * DI]);
                a0 = fmaf(f.x, wk0[k], a0); a1 = fmaf(f.y, wk1[k], a1);
            }
        }
    }
    ((__half2*)uh)[(size_t)(b * L_ + t) * (DI / 2) + d2] =
        __floats2half2_rn(siluf(a0), siluf(a1));
}

// ---------------- selective scan + gating (64-step tiles, 16-step reduce) ----------------
// sBC packed half2 -> halved smem crossbar traffic in the serial loop.
__global__ void __launch_bounds__(256)
scan_kernel(const float* __restrict__ delta,
            const half* __restrict__ uh,
            const float* __restrict__ dbc,
            const float* __restrict__ A_log,
            const float* __restrict__ Dp,
            const half* __restrict__ xzh,
            half* __restrict__ yh) {
    const int lane = threadIdx.x & 31;
    const int w    = threadIdx.x >> 5;            // 0..7
    const int d0   = blockIdx.x * 8;
    const int b    = blockIdx.y;

    __shared__ __half2 sBC[64][32];               // [t][s] = (B, C) fp16
    __shared__ float2  sDP[64][8];                // [t][w] = (delta, delta*u)
    __shared__ float   sh[64][9];                 // output transpose, padded

    const float A2 = -expf(A_log[(d0 + w) * DS + lane]) * 1.4426950408889634f;

    const int lt = threadIdx.x >> 3;              // 0..31
    const int lq = threadIdx.x & 7;               // 0..7
    const float Dv = Dp[d0 + lq];

    float h = 0.f;

    for (int t0 = 0; t0 < L_; t0 += 64) {
        float uu[2], zz[2];
#pragma unroll
        for (int rr = 0; rr < 2; rr++) {
            const int row = lt + rr * 32;
            const size_t lrow = (size_t)(b * L_ + t0 + row);
            const float4* src = (const float4*)(dbc + lrow * 128 + 64);
            const float4 B4 = src[lq];
            const float4 C4 = src[lq + 8];
            sBC[row][lq * 4 + 0] = __floats2half2_rn(B4.x, C4.x);
            sBC[row][lq * 4 + 1] = __floats2half2_rn(B4.y, C4.y);
            sBC[row][lq * 4 + 2] = __floats2half2_rn(B4.z, C4.z);
            sBC[row][lq * 4 + 3] = __floats2half2_rn(B4.w, C4.w);
            const float dl = delta[lrow * DI + d0 + lq];
            uu[rr] = __half2float(uh[lrow * DI + d0 + lq]);
            zz[rr] = __half2float(xzh[lrow * (size_t)(2 * DI) + DI + d0 + lq]);
            sDP[row][lq] = make_float2(dl, dl * uu[rr]);
        }
        __syncthreads();

#pragma unroll
        for (int ch = 0; ch < 4; ch++) {
            float v[16];
#pragma unroll
            for (int ti = 0; ti < 16; ti++) {
                const int tt = ch * 16 + ti;
                const float2 dp = sDP[tt][w];
                const float2 bc = __half22float2(sBC[tt][lane]);
                h = fmaf(ex2f(dp.x * A2), h, dp.y * bc.x);
                v[ti] = h * bc.y;
            }
            const bool hi8 = (lane & 8) != 0;
#pragma unroll
            for (int j = 0; j < 8; j++) {
                float send = hi8 ? v[j] : v[j + 8];
                float r = __shfl_xor_sync(0xffffffffu, send, 8);
                v[j] = (hi8 ? v[j + 8] : v[j]) + r;
            }
            const bool hi4 = (lane & 4) != 0;
#pragma unroll
            for (int j = 0; j < 4; j++) {
                float send = hi4 ? v[j] : v[j + 4];
                float r = __shfl_xor_sync(0xffffffffu, send, 4);
                v[j] = (hi4 ? v[j + 4] : v[j]) + r;
            }
            const bool hi2 = (lane & 2) != 0;
#pragma unroll
            for (int j = 0; j < 2; j++) {
                float send = hi2 ? v[j] : v[j + 2];
                float r = __shfl_xor_sync(0xffffffffu, send, 2);
                v[j] = (hi2 ? v[j + 2] : v[j]) + r;
            }
            const bool hi1 = (lane & 1) != 0;
            {
                float send = hi1 ? v[0] : v[1];
                float r = __shfl_xor_sync(0xffffffffu, send, 1);
                v[0] = (hi1 ? v[1] : v[0]) + r;
            }
            v[0] += __shfl_xor_sync(0xffffffffu, v[0], 16);
            if (lane < 16) sh[ch * 16 + lane][w] = v[0];
        }
        __syncthreads();

#pragma unroll
        for (int rr = 0; rr < 2; rr++) {
            const int row = lt + rr * 32;
            const size_t lrow = (size_t)(b * L_ + t0 + row);
            const float yv = sh[row][lq];
            const float yf = (yv + uu[rr] * Dv) * siluf(zz[rr]);
            yh[lrow * DI + d0 + lq] = __float2half(yf);
        }
        __syncthreads();
    }
}

// ---------------- in-place LayerNorm (row = 1024) ----------------
__global__ void ln_kernel(float* __restrict__ out,
                          const float* __restrict__ gamma,
                          const float* __restrict__ beta) {
    const int row = blockIdx.x;
    float4* p = (float4*)(out + (size_t)row * DM);
    const int i = threadIdx.x;

    float4 x = p[i];
    float s = x.x + x.y + x.z + x.w;
    float q = x.x * x.x + x.y * x.y + x.z * x.z + x.w * x.w;
#pragma unroll
    for (int o = 16; o; o >>= 1) {
        s += __shfl_xor_sync(0xffffffffu, s, o);
        q += __shfl_xor_sync(0xffffffffu, q, o);
    }
    __shared__ float rs[8], rq[8];
    if ((i & 31) == 0) { rs[i >> 5] = s; rq[i >> 5] = q; }
    __syncthreads();
    s = 0.f; q = 0.f;
#pragma unroll
    for (int k = 0; k < 8; k++) { s += rs[k]; q += rq[k]; }

    const float mu  = s * (1.f / DM);
    const float var = q * (1.f / DM) - mu * mu;
    const float inv = rsqrtf(var + LN_EPS);

    const float4 gg = ((const float4*)gamma)[i];
    const float4 bb = ((const float4*)beta)[i];
    x.x = (x.x - mu) * inv * gg.x + bb.x;
    x.y = (x.y - mu) * inv * gg.y + bb.y;
    x.z = (x.z - mu) * inv * gg.z + bb.z;
    x.w = (x.w - mu) * inv * gg.w + bb.w;
    p[i] = x;
}

// ---------------- launch (R13 structure) ----------------
extern "C" void kernel_launch(void* const* d_in, const int* in_sizes, int n_in,
                              void* d_out, int out_size) {
    (void)in_sizes; (void)n_in; (void)out_size;
    const float* x         = (const float*)d_in[0];
    const float* in_proj_w = (const float*)d_in[1];
    const float* conv_w    = (const float*)d_in[2];
    const float* conv_b    = (const float*)d_in[3];
    const float* x_proj_w  = (const float*)d_in[4];
    const float* dt_proj_w = (const float*)d_in[5];
    const float* dt_proj_b = (const float*)d_in[6];
    const float* A_log     = (const float*)d_in[7];
    const float* Dp        = (const float*)d_in[8];
    const float* out_proj_w= (const float*)d_in[9];
    const float* ln_gamma  = (const float*)d_in[10];
    const float* ln_beta   = (const float*)d_in[11];
    float* out = (float*)d_out;

    float *dbc, *delta;
    half *xzh, *xh, *uh, *dth, *yh;
    half *win, *wxp, *wdt, *wout;
    cudaGetSymbolAddress((void**)&dbc,   g_dbc);
    cudaGetSymbolAddress((void**)&delta, g_delta);
    cudaGetSymbolAddress((void**)&xzh,   g_xzh);
    cudaGetSymbolAddress((void**)&xh,    g_xh);
    cudaGetSymbolAddress((void**)&uh,    g_uh);
    cudaGetSymbolAddress((void**)&dth,   g_dth);
    cudaGetSymbolAddress((void**)&yh,    g_yh);
    cudaGetSymbolAddress((void**)&win,   g_win);
    cudaGetSymbolAddress((void**)&wxp,   g_wxp);
    cudaGetSymbolAddress((void**)&wdt,   g_wdt);
    cudaGetSymbolAddress((void**)&wout,  g_wout);

    constexpr int SMEM_P3 = 3 * STGB;          // 61440
    constexpr int STG_XP  = APB + 64 * ROWB;   // 15360
    constexpr int SMEM_XP = 2 * STG_XP;        // 30720
    cudaFuncSetAttribute(mma_gemm<0>, cudaFuncAttributeMaxDynamicSharedMemorySize, SMEM_P3);
    cudaFuncSetAttribute(mma_gemm<1>, cudaFuncAttributeMaxDynamicSharedMemorySize, SMEM_P3);
    cudaFuncSetAttribute(mma_gemm<3>, cudaFuncAttributeMaxDynamicSharedMemorySize, SMEM_P3);
    cudaFuncSetAttribute(mma_gemm_xp, cudaFuncAttributeMaxDynamicSharedMemorySize, SMEM_XP);

    // streams/events for graph fork-join (created once; handles only)
    static cudaStream_t s1 = nullptr, s2 = nullptr;
    static cudaEvent_t e0 = nullptr, e_win = nullptr, e_xh = nullptr,
                       e_w = nullptr, e_z = nullptr;
    if (s1 == nullptr) {
        cudaStreamCreateWithFlags(&s1, cudaStreamNonBlocking);
        cudaStreamCreateWithFlags(&s2, cudaStreamNonBlocking);
        cudaEventCreateWithFlags(&e0,    cudaEventDisableTiming);
        cudaEventCreateWithFlags(&e_win, cudaEventDisableTiming);
        cudaEventCreateWithFlags(&e_xh,  cudaEventDisableTiming);
        cudaEventCreateWithFlags(&e_w,   cudaEventDisableTiming);
        cudaEventCreateWithFlags(&e_z,   cudaEventDisableTiming);
    }

    // fork point
    cudaEventRecord(e0, 0);

    // --- s1: x convert, then (after win) the z-half GEMM ---
    cudaStreamWaitEvent(s1, e0, 0);
    conv16_kernel<<<(M_*DM/2 + 255)/256, 256, 0, s1>>>(
        (const float2*)x, (uint32_t*)xh, M_*DM/2);
    cudaEventRecord(e_xh, s1);

    // --- s2: weight transposes needed from x_proj onward ---
    cudaStreamWaitEvent(s2, e0, 0);
    tconv_kernel<<<dim3(128/32, DI/32), dim3(32,8), 0, s2>>>(x_proj_w,  wxp,  DI, 128);
    tconv_kernel<<<dim3(DI/32,  DR/32), dim3(32,8), 0, s2>>>(dt_proj_w, wdt,  DR, DI);
    tconv_kernel<<<dim3(DM/32,  DI/32), dim3(32,8), 0, s2>>>(out_proj_w, wout, DI, DM);
    cudaEventRecord(e_w, s2);

    // --- default: in_proj weight transpose ---
    tconv_kernel<<<dim3(4096/32, DM/32), dim3(32,8)>>>(in_proj_w, win, DM, 4096);
    cudaEventRecord(e_win, 0);

    // --- s1: z half of in_proj (cols 2048..4095) ---
    cudaStreamWaitEvent(s1, e_win, 0);
    mma_gemm<3><<<dim3(16, M_/128), 256, SMEM_P3, s1>>>(
        xh, win + (size_t)2048 * DM, nullptr, (float*)(xzh + 2048), DM, 4096);
    cudaEventRecord(e_z, s1);

    // --- default: xi half of in_proj (cols 0..2047) ---
    cudaStreamWaitEvent(0, e_xh, 0);
    mma_gemm<3><<<dim3(16, M_/128), 256, SMEM_P3>>>(
        xh, win, nullptr, (float*)xzh, DM, 4096);

    conv_silu_kernel<<<(M_*DI/2 + 255)/256, 256>>>(xzh, conv_w, conv_b, uh);

    cudaStreamWaitEvent(0, e_w, 0);
    mma_gemm_xp<<<dim3(2, M_/128), 256, SMEM_XP>>>(uh, wxp, dbc, dth, DI, 128);

    mma_gemm<1><<<dim3(DI/128, M_/128), 256, SMEM_P3>>>(
        dth, wdt, dt_proj_b, delta, DR, DI);

    cudaStreamWaitEvent(0, e_z, 0);
    scan_kernel<<<dim3(DI/8, B_), 256>>>(delta, uh, dbc, A_log, Dp, xzh, yh);

    mma_gemm<0><<<dim3(DM/128, M_/128), 256, SMEM_P3>>>(
        yh, wout, nullptr, out, DI, DM);

    ln_kernel<<<M_, 256>>>(out, ln_gamma, ln_beta);
}